// round 2
// baseline (speedup 1.0000x reference)
#include <cuda_runtime.h>
#include <math.h>

// Problem constants (fixed shapes)
#define Bb 32
#define Cc 3
#define Hh 256
#define Ww 832
#define HWsz (Hh*Ww)          // 212992
#define BC (Bb*Cc)            // 96
#define KDET 100
#define QPR (Ww/4)            // 208 float4-quads per row
#define QPS (Hh*QPR)          // 53248 quads per slice
#define BLKNMS 256
#define NBLK_PER_SLICE (QPS/BLKNMS)   // 208

#define PI_F 3.14159265358979323846f
#define HALF_PI_F 1.57079632679489661923f

// ---------------- scratch (device globals; no runtime allocation) ----------------
__device__ unsigned long long g_cand[(size_t)BC * HWsz];   // worst-case survivor list
__device__ int                g_cnt[BC];
__device__ unsigned long long g_top1[BC * KDET];           // per-(b,c) top-100 keys

// key layout: [63:32] = float bits of value (value >= 0 so monotonic as uint)
//             [31:0]  = 0xFFFFFFFF - pixel_index  (larger = smaller index)
// descending key sort == jax top_k order (desc value, stable lower-index-first)

__global__ void zero_counters() {
    int i = threadIdx.x;
    if (i < BC) g_cnt[i] = 0;
}

// ---------------- kernel 1: fused 3x3 NMS + survivor append ----------------
__device__ __forceinline__ float4 ld4_or_ninf(const float* base, int yy, int xx) {
    if ((unsigned)yy < (unsigned)Hh && xx >= 0 && xx < Ww) {
        return *(const float4*)(base + yy * Ww + xx);
    }
    float ninf = __int_as_float(0xff800000);
    return make_float4(ninf, ninf, ninf, ninf);
}

__global__ void nms_collect(const float* __restrict__ hm) {
    int slice = blockIdx.x / NBLK_PER_SLICE;       // bc in [0,96)
    int blk   = blockIdx.x % NBLK_PER_SLICE;
    int q     = blk * BLKNMS + threadIdx.x;        // quad id within slice
    int y     = q / QPR;
    int x4    = (q - y * QPR) * 4;

    const float* base = hm + (size_t)slice * HWsz;

    float w[3][12];
#pragma unroll
    for (int r = 0; r < 3; r++) {
        int yy = y + r - 1;
#pragma unroll
        for (int s = 0; s < 3; s++) {
            float4 v = ld4_or_ninf(base, yy, x4 + (s - 1) * 4);
            w[r][s*4+0] = v.x; w[r][s*4+1] = v.y; w[r][s*4+2] = v.z; w[r][s*4+3] = v.w;
        }
    }

    unsigned lane = threadIdx.x & 31u;
#pragma unroll
    for (int j = 0; j < 4; j++) {
        float v = w[1][4 + j];
        float m = v;
#pragma unroll
        for (int r = 0; r < 3; r++) {
            m = fmaxf(m, fmaxf(w[r][3 + j], fmaxf(w[r][4 + j], w[r][5 + j])));
        }
        bool surv = (v >= m);   // v == window max  (window includes v)
        unsigned bal = __ballot_sync(0xffffffffu, surv);
        if (bal) {
            int leader = __ffs(bal) - 1;
            int cnt = __popc(bal);
            int basei = 0;
            if ((int)lane == leader) basei = atomicAdd(&g_cnt[slice], cnt);
            basei = __shfl_sync(0xffffffffu, basei, leader);
            if (surv) {
                int rank = __popc(bal & ((1u << lane) - 1u));
                unsigned pix = (unsigned)(y * Ww + x4 + j);
                unsigned long long key =
                    ((unsigned long long)__float_as_uint(v) << 32) |
                    (unsigned long long)(0xFFFFFFFFu - pix);
                g_cand[(size_t)slice * HWsz + basei + rank] = key;
            }
        }
    }
}

// ---------------- bitonic sort (descending) ----------------
template <int M>
__device__ void bitonic_desc(unsigned long long* buf, int tid, int nt) {
    for (int k = 2; k <= M; k <<= 1) {
        for (int j = k >> 1; j > 0; j >>= 1) {
            for (int i = tid; i < M; i += nt) {
                int ij = i ^ j;
                if (ij > i) {
                    bool dir = ((i & k) == 0);          // true -> descending segment
                    unsigned long long a = buf[i], b = buf[ij];
                    if ((a < b) == dir) { buf[i] = b; buf[ij] = a; }
                }
            }
            __syncthreads();
        }
    }
}

// ---------------- kernel 2: per-(b,c) exact top-100 via 2-level radix select ----------------
__global__ void select_topk() {
    __shared__ int hist[4096];
    __shared__ unsigned long long buf[2048];
    __shared__ int s_b1, s_pre1, s_thr, s_m;

    int bc  = blockIdx.x;
    int tid = threadIdx.x;
    int nt  = blockDim.x;
    int n   = g_cnt[bc];
    const unsigned long long* cand = g_cand + (size_t)bc * HWsz;

    for (int i = tid; i < 4096; i += nt) hist[i] = 0;
    if (tid == 0) { s_b1 = -1; s_pre1 = 0; s_thr = 0; s_m = 0; }
    __syncthreads();

    // level 1: 12-bit bins of top value bits (key >> 52)
    for (int i = tid; i < n; i += nt) atomicAdd(&hist[(int)(cand[i] >> 52)], 1);
    __syncthreads();
    if (tid == 0) {
        int cum = 0;
        for (int b = 4095; b >= 0; b--) {
            int c = hist[b];
            if (cum + c >= KDET) { s_b1 = b; s_pre1 = cum; break; }
            cum += c;
        }
        if (s_b1 < 0) { s_b1 = 0; s_pre1 = 0; }   // fewer than K candidates: take all
    }
    __syncthreads();
    int b1 = s_b1;

    // level 2: next 8 bits within bucket b1
    for (int i = tid; i < 256; i += nt) hist[i] = 0;
    __syncthreads();
    for (int i = tid; i < n; i += nt) {
        unsigned long long k = cand[i];
        if ((int)(k >> 52) == b1) atomicAdd(&hist[(int)((k >> 44) & 255)], 1);
    }
    __syncthreads();
    if (tid == 0) {
        int cum = s_pre1;
        int b2sel = 0;
        for (int b = 255; b >= 0; b--) {
            int c = hist[b];
            if (cum + c >= KDET) { b2sel = b; break; }
            cum += c;
        }
        s_thr = (b1 << 8) | b2sel;
    }
    __syncthreads();

    // collect everything at/above the 20-bit threshold
    unsigned long long thr = (unsigned long long)s_thr;
    for (int i = tid; i < n; i += nt) {
        unsigned long long k = cand[i];
        if ((k >> 44) >= thr) {
            int p = atomicAdd(&s_m, 1);
            if (p < 2048) buf[p] = k;
        }
    }
    __syncthreads();
    int m = min(s_m, 2048);
    for (int i = tid + m; i < 2048; i += nt) buf[i] = 0xFFFFFFFFull;  // score 0, pix 0
    __syncthreads();

    bitonic_desc<2048>(buf, tid, nt);

    if (tid < KDET) g_top1[bc * KDET + tid] = buf[tid];
}

// ---------------- kernel 3: per-batch 300->100 top-k + geometry epilogue ----------------
__global__ void finalize(const float* __restrict__ reg,
                         const float* __restrict__ trans,
                         const float* __restrict__ Kmat,
                         const float* __restrict__ size2,
                         const float* __restrict__ hcam,
                         const float* __restrict__ dimsIn,
                         float* __restrict__ out) {
    __shared__ unsigned long long buf[512];
    __shared__ unsigned pixs[300];

    int b = blockIdx.x, tid = threadIdx.x, nt = blockDim.x;

    for (int i = tid; i < 512; i += nt) {
        if (i < 300) {
            unsigned long long k1 = g_top1[b * 300 + i];   // i = c*100 + j
            unsigned pix = 0xFFFFFFFFu - (unsigned)(k1 & 0xFFFFFFFFu);
            if (pix >= (unsigned)HWsz) pix = 0;
            pixs[i] = pix;
            // re-key with flattened C*K position for the second-stage tie-break
            buf[i] = (k1 & 0xFFFFFFFF00000000ull) |
                     (unsigned long long)(0xFFFFFFFFu - (unsigned)i);
        } else {
            buf[i] = 0ull;
        }
    }
    __syncthreads();

    bitonic_desc<512>(buf, tid, nt);

    if (tid < KDET) {
        unsigned long long k = buf[tid];
        float score = __uint_as_float((unsigned)(k >> 32));
        unsigned flat = 0xFFFFFFFFu - (unsigned)(k & 0xFFFFFFFFu);
        int clsI = 0; unsigned pix = 0;
        if (flat < 300u) { clsI = flat / 100; pix = pixs[flat]; }

        int ysI = pix / Ww;
        int xsI = pix - ysI * Ww;
        float xs = (float)xsI, ys = (float)ysI;

        const float* rb = reg + (size_t)b * 4 * HWsz;
        float dv_delta = rb[0 * HWsz + pix];
        float off_u    = rb[1 * HWsz + pix];
        float ori0     = rb[2 * HWsz + pix];
        float ori1     = rb[3 * HWsz + pix];

        // 3x3 inverse of trans_mat (first two rows needed)
        const float* T = trans + b * 9;
        float a00=T[0],a01=T[1],a02=T[2],a10=T[3],a11=T[4],a12=T[5],a20=T[6],a21=T[7],a22=T[8];
        float det = a00*(a11*a22 - a12*a21) - a01*(a10*a22 - a12*a20) + a02*(a10*a21 - a11*a20);
        float id = 1.0f / det;
        float i00=(a11*a22-a12*a21)*id, i01=(a02*a21-a01*a22)*id, i02=(a01*a12-a02*a11)*id;
        float i10=(a12*a20-a10*a22)*id, i11=(a00*a22-a02*a20)*id, i12=(a02*a10-a00*a12)*id;

        float ptx = xs + off_u, pty = ys;
        float img_x = i00*ptx + i01*pty + i02;
        float img_y = i10*ptx + i11*pty + i12;   (void)img_y;

        const float* Km = Kmat + b * 9;
        float fx = Km[0], cxk = Km[2], fy = Km[4];

        float h = hcam[b];
        float d0 = dimsIn[b*3+0], d1 = dimsIn[b*3+1], d2 = dimsIn[b*3+2];
        if (!isfinite(d0)) d0 = 3.88f;
        if (!isfinite(d1)) d1 = 1.63f;
        if (!isfinite(d2)) d2 = 1.53f;

        float h_ref = h - d1 * 0.5f;
        float fyh = fy * fabsf(h_ref);
        float log_dv_ref = logf(fmaxf(fyh, 1e-7f) / 28.01f);
        float log_dv = fminf(fmaxf(log_dv_ref + dv_delta, -4.0f), 8.0f);
        float depth = fminf(fmaxf(fyh * expf(-log_dv), 0.5f), 120.0f);
        float pxl = (img_x - cxk) * depth / fx;

        float ray = atanf(pxl / (depth + 1e-7f));
        float alpha = atanf(ori0 / (ori1 + 1e-7f)) + (ori1 >= 0.0f ? -HALF_PI_F : HALF_PI_F);
        float roty = alpha + ray;
        if (roty >  PI_F) roty -= 2.0f * PI_F;
        if (roty < -PI_F) roty += 2.0f * PI_F;
        float cs = cosf(roty), sn = sinf(roty);

        const float cx8[8] = {-0.5f, 0.5f, 0.5f, 0.5f, 0.5f,-0.5f,-0.5f,-0.5f};
        const float cy8[8] = {-1.0f,-1.0f, 0.0f, 0.0f,-1.0f,-1.0f, 0.0f, 0.0f};
        const float cz8[8] = {-0.5f,-0.5f,-0.5f, 0.5f, 0.5f, 0.5f, 0.5f,-0.5f};

        float umin =  3.4e38f, umax = -3.4e38f, vmin = 3.4e38f, vmax = -3.4e38f;
#pragma unroll
        for (int i = 0; i < 8; i++) {
            float xc = d0 * cx8[i], yc = d1 * cy8[i], zc = d2 * cz8[i];
            float bx =  cs * xc + sn * zc + pxl;
            float by =  yc + h;
            float bz = -sn * xc + cs * zc + depth;
            float up = Km[0]*bx + Km[1]*by + Km[2]*bz;
            float vp = Km[3]*bx + Km[4]*by + Km[5]*bz;
            float wp = Km[6]*bx + Km[7]*by + Km[8]*bz;
            float u = up / wp, v = vp / wp;
            umin = fminf(umin, u); umax = fmaxf(umax, u);
            vmin = fminf(vmin, v); vmax = fmaxf(vmax, v);
        }
        float img_w = size2[0], img_h = size2[1];
        float xmin = fminf(fmaxf(umin, 0.0f), img_w);
        float xmax = fminf(fmaxf(umax, 0.0f), img_w);
        float ymin = fminf(fmaxf(vmin, 0.0f), img_h);
        float ymax = fminf(fmaxf(vmax, 0.0f), img_h);

        float keep = (score > 0.25f) ? 1.0f : 0.0f;

        float o[14];
        o[0]  = (float)clsI;
        o[1]  = alpha;
        o[2]  = xmin; o[3] = ymin; o[4] = xmax; o[5] = ymax;
        o[6]  = d1;   o[7] = d2;   o[8] = d0;          // roll(dims, -1)
        o[9]  = pxl;  o[10] = h;   o[11] = depth;
        o[12] = roty;
        o[13] = score;

        float* dst = out + (size_t)(b * KDET + tid) * 14;
#pragma unroll
        for (int c = 0; c < 14; c++) dst[c] = o[c] * keep;
    }
}

// ---------------- launch ----------------
extern "C" void kernel_launch(void* const* d_in, const int* in_sizes, int n_in,
                              void* d_out, int out_size) {
    const float* hm    = (const float*)d_in[0];
    const float* reg   = (const float*)d_in[1];
    const float* trans = (const float*)d_in[2];
    const float* Kmat  = (const float*)d_in[3];
    const float* size2 = (const float*)d_in[4];
    const float* hcam  = (const float*)d_in[5];
    const float* dims  = (const float*)d_in[6];
    float* out = (float*)d_out;

    zero_counters<<<1, 128>>>();
    nms_collect<<<BC * NBLK_PER_SLICE, BLKNMS>>>(hm);
    select_topk<<<BC, 256>>>();
    finalize<<<Bb, 128>>>(reg, trans, Kmat, size2, hcam, dims, out);
}

// round 4
// speedup vs baseline: 2.6342x; 2.6342x over previous
#include <cuda_runtime.h>
#include <math.h>

// Problem constants (fixed shapes)
#define Bb 32
#define Cc 3
#define Hh 256
#define Ww 832
#define HWsz (Hh*Ww)          // 212992
#define BC (Bb*Cc)            // 96
#define KDET 100
#define QPR (Ww/4)            // 208 float4-quads per row
#define QPS (Hh*QPR)          // 53248 quads per slice
#define BLKNMS 256
#define NBLK_PER_SLICE (QPS/BLKNMS)   // 208

#define PI_F 3.14159265358979323846f
#define HALF_PI_F 1.57079632679489661923f

// ---------------- scratch (device globals; no runtime allocation) ----------------
__device__ unsigned long long g_cand[(size_t)BC * HWsz];   // worst-case survivor list
__device__ int                g_cnt[BC];
__device__ unsigned long long g_top1[BC * KDET];           // per-(b,c) top-100 keys

// key layout: [63:32] = float bits of value (value >= 0 so monotonic as uint)
//             [31:0]  = 0xFFFFFFFF - pixel_index  (larger = smaller index)
// descending key sort == jax top_k order (desc value, stable lower-index-first)

__global__ void zero_counters() {
    int i = threadIdx.x;
    if (i < BC) g_cnt[i] = 0;
}

// ---------------- kernel 1: fused 3x3 NMS + block-compacted survivor append ----------------
__device__ __forceinline__ float4 ld4_or_ninf(const float* base, int yy, int xx) {
    if ((unsigned)yy < (unsigned)Hh && xx >= 0 && xx < Ww) {
        return *(const float4*)(base + yy * Ww + xx);
    }
    float ninf = __int_as_float(0xff800000);
    return make_float4(ninf, ninf, ninf, ninf);
}

__device__ __forceinline__ float fmax3(float a, float b, float c) {
    return fmaxf(a, fmaxf(b, c));
}

__global__ void nms_collect(const float* __restrict__ hm) {
    __shared__ unsigned long long sbuf[1024];   // worst case: every pixel survives (all-ties)
    __shared__ int scnt;
    __shared__ int sbase;

    int slice = blockIdx.x / NBLK_PER_SLICE;       // bc in [0,96)
    int blk   = blockIdx.x % NBLK_PER_SLICE;
    int q     = blk * BLKNMS + threadIdx.x;        // quad id within slice
    int y     = q / QPR;
    int x4    = (q - y * QPR) * 4;

    if (threadIdx.x == 0) scnt = 0;
    __syncthreads();

    const float* base = hm + (size_t)slice * HWsz;

    float w[3][12];
#pragma unroll
    for (int r = 0; r < 3; r++) {
        int yy = y + r - 1;
#pragma unroll
        for (int s = 0; s < 3; s++) {
            float4 v = ld4_or_ninf(base, yy, x4 + (s - 1) * 4);
            w[r][s*4+0] = v.x; w[r][s*4+1] = v.y; w[r][s*4+2] = v.z; w[r][s*4+3] = v.w;
        }
    }

    // column max of the 3 rows, then 3-wide row max per pixel
    float cm[12];
#pragma unroll
    for (int s = 0; s < 12; s++) cm[s] = fmax3(w[0][s], w[1][s], w[2][s]);

    unsigned lane = threadIdx.x & 31u;
#pragma unroll
    for (int j = 0; j < 4; j++) {
        float v = w[1][4 + j];
        float m = fmax3(cm[3 + j], cm[4 + j], cm[5 + j]);   // includes v
        bool surv = (v >= m);
        unsigned bal = __ballot_sync(0xffffffffu, surv);
        if (bal) {
            int leader = __ffs(bal) - 1;
            int cnt = __popc(bal);
            int basei = 0;
            if ((int)lane == leader) basei = atomicAdd(&scnt, cnt);
            basei = __shfl_sync(0xffffffffu, basei, leader);
            if (surv) {
                int rank = __popc(bal & ((1u << lane) - 1u));
                unsigned pix = (unsigned)(y * Ww + x4 + j);
                unsigned long long key =
                    ((unsigned long long)__float_as_uint(v) << 32) |
                    (unsigned long long)(0xFFFFFFFFu - pix);
                sbuf[basei + rank] = key;
            }
        }
    }
    __syncthreads();

    int c = scnt;
    if (threadIdx.x == 0) sbase = atomicAdd(&g_cnt[slice], c);
    __syncthreads();

    unsigned long long* dst = g_cand + (size_t)slice * HWsz + sbase;
    for (int i = threadIdx.x; i < c; i += BLKNMS) dst[i] = sbuf[i];
}

// ---------------- bitonic sort (descending) ----------------
template <int M>
__device__ void bitonic_desc(unsigned long long* buf, int tid, int nt) {
    for (int k = 2; k <= M; k <<= 1) {
        for (int j = k >> 1; j > 0; j >>= 1) {
            for (int i = tid; i < M; i += nt) {
                int ij = i ^ j;
                if (ij > i) {
                    bool dir = ((i & k) == 0);          // true -> descending segment
                    unsigned long long a = buf[i], b = buf[ij];
                    if ((a < b) == dir) { buf[i] = b; buf[ij] = a; }
                }
            }
            __syncthreads();
        }
    }
}

// ---------------- kernel 2: per-(b,c) exact top-100 via 2-level radix select ----------------
__global__ void select_topk() {
    __shared__ int hist[4096];
    __shared__ unsigned long long buf[2048];
    __shared__ int s_b1, s_pre1, s_thr, s_m;

    int bc  = blockIdx.x;
    int tid = threadIdx.x;
    int nt  = blockDim.x;
    int n   = g_cnt[bc];
    const unsigned long long* cand = g_cand + (size_t)bc * HWsz;

    for (int i = tid; i < 4096; i += nt) hist[i] = 0;
    if (tid == 0) { s_b1 = -1; s_pre1 = 0; s_thr = 0; s_m = 0; }
    __syncthreads();

    // level 1: 12-bit bins of top value bits (key >> 52)
    for (int i = tid; i < n; i += nt) atomicAdd(&hist[(int)(cand[i] >> 52)], 1);
    __syncthreads();
    if (tid == 0) {
        int cum = 0;
        for (int b = 4095; b >= 0; b--) {
            int c = hist[b];
            if (cum + c >= KDET) { s_b1 = b; s_pre1 = cum; break; }
            cum += c;
        }
        if (s_b1 < 0) { s_b1 = 0; s_pre1 = 0; }   // fewer than K candidates: take all
    }
    __syncthreads();
    int b1 = s_b1;

    // level 2: next 8 bits within bucket b1
    for (int i = tid; i < 256; i += nt) hist[i] = 0;
    __syncthreads();
    for (int i = tid; i < n; i += nt) {
        unsigned long long k = cand[i];
        if ((int)(k >> 52) == b1) atomicAdd(&hist[(int)((k >> 44) & 255)], 1);
    }
    __syncthreads();
    if (tid == 0) {
        int cum = s_pre1;
        int b2sel = 0;
        for (int b = 255; b >= 0; b--) {
            int c = hist[b];
            if (cum + c >= KDET) { b2sel = b; break; }
            cum += c;
        }
        s_thr = (b1 << 8) | b2sel;
    }
    __syncthreads();

    // collect everything at/above the 20-bit threshold
    unsigned long long thr = (unsigned long long)s_thr;
    for (int i = tid; i < n; i += nt) {
        unsigned long long k = cand[i];
        if ((k >> 44) >= thr) {
            int p = atomicAdd(&s_m, 1);
            if (p < 2048) buf[p] = k;
        }
    }
    __syncthreads();
    int m = min(s_m, 2048);
    for (int i = tid + m; i < 2048; i += nt) buf[i] = 0xFFFFFFFFull;  // score 0, pix 0
    __syncthreads();

    bitonic_desc<2048>(buf, tid, nt);

    if (tid < KDET) g_top1[bc * KDET + tid] = buf[tid];
}

// ---------------- kernel 3: per-batch 300->100 top-k + geometry epilogue ----------------
__global__ void finalize(const float* __restrict__ reg,
                         const float* __restrict__ trans,
                         const float* __restrict__ Kmat,
                         const float* __restrict__ size2,
                         const float* __restrict__ hcam,
                         const float* __restrict__ dimsIn,
                         float* __restrict__ out) {
    __shared__ unsigned long long buf[512];
    __shared__ unsigned pixs[300];
    __shared__ float s_reg[300][4];

    int b = blockIdx.x, tid = threadIdx.x, nt = blockDim.x;

    for (int i = tid; i < 512; i += nt) {
        if (i < 300) {
            unsigned long long k1 = g_top1[b * 300 + i];   // i = c*100 + j
            unsigned pix = 0xFFFFFFFFu - (unsigned)(k1 & 0xFFFFFFFFu);
            if (pix >= (unsigned)HWsz) pix = 0;
            pixs[i] = pix;
            // re-key with flattened C*K position for the second-stage tie-break
            buf[i] = (k1 & 0xFFFFFFFF00000000ull) |
                     (unsigned long long)(0xFFFFFFFFu - (unsigned)i);
        } else {
            buf[i] = 0ull;
        }
    }
    __syncthreads();

    // Prefetch all candidates' regression gathers (parallel MLP instead of a
    // post-sort dependent latency chain). Ordered before use by the sort's syncs.
    const float* rb = reg + (size_t)b * 4 * HWsz;
    for (int i = tid; i < 300; i += nt) {
        unsigned pix = pixs[i];
        s_reg[i][0] = rb[0 * HWsz + pix];
        s_reg[i][1] = rb[1 * HWsz + pix];
        s_reg[i][2] = rb[2 * HWsz + pix];
        s_reg[i][3] = rb[3 * HWsz + pix];
    }

    bitonic_desc<512>(buf, tid, nt);

    if (tid < KDET) {
        unsigned long long k = buf[tid];
        float score = __uint_as_float((unsigned)(k >> 32));
        unsigned flat = 0xFFFFFFFFu - (unsigned)(k & 0xFFFFFFFFu);
        int clsI = 0; unsigned pix = 0;
        float dv_delta = 0.f, off_u = 0.f, ori0 = 0.f, ori1 = 0.f;
        if (flat < 300u) {
            clsI = flat / 100; pix = pixs[flat];
            dv_delta = s_reg[flat][0];
            off_u    = s_reg[flat][1];
            ori0     = s_reg[flat][2];
            ori1     = s_reg[flat][3];
        }

        int ysI = pix / Ww;
        int xsI = pix - ysI * Ww;
        float xs = (float)xsI, ys = (float)ysI;

        // 3x3 inverse of trans_mat (first row needed for img_x)
        const float* T = trans + b * 9;
        float a00=T[0],a01=T[1],a02=T[2],a10=T[3],a11=T[4],a12=T[5],a20=T[6],a21=T[7],a22=T[8];
        float det = a00*(a11*a22 - a12*a21) - a01*(a10*a22 - a12*a20) + a02*(a10*a21 - a11*a20);
        float id = 1.0f / det;
        float i00=(a11*a22-a12*a21)*id, i01=(a02*a21-a01*a22)*id, i02=(a01*a12-a02*a11)*id;

        float ptx = xs + off_u, pty = ys;
        float img_x = i00*ptx + i01*pty + i02;

        const float* Km = Kmat + b * 9;
        float fx = Km[0], cxk = Km[2], fy = Km[4];

        float h = hcam[b];
        float d0 = dimsIn[b*3+0], d1 = dimsIn[b*3+1], d2 = dimsIn[b*3+2];
        if (!isfinite(d0)) d0 = 3.88f;
        if (!isfinite(d1)) d1 = 1.63f;
        if (!isfinite(d2)) d2 = 1.53f;

        float h_ref = h - d1 * 0.5f;
        float fyh = fy * fabsf(h_ref);
        float log_dv_ref = logf(fmaxf(fyh, 1e-7f) / 28.01f);
        float log_dv = fminf(fmaxf(log_dv_ref + dv_delta, -4.0f), 8.0f);
        float depth = fminf(fmaxf(fyh * expf(-log_dv), 0.5f), 120.0f);
        float pxl = (img_x - cxk) * depth / fx;

        float ray = atanf(pxl / (depth + 1e-7f));
        float alpha = atanf(ori0 / (ori1 + 1e-7f)) + (ori1 >= 0.0f ? -HALF_PI_F : HALF_PI_F);
        float roty = alpha + ray;
        if (roty >  PI_F) roty -= 2.0f * PI_F;
        if (roty < -PI_F) roty += 2.0f * PI_F;
        float cs = cosf(roty), sn = sinf(roty);

        const float cx8[8] = {-0.5f, 0.5f, 0.5f, 0.5f, 0.5f,-0.5f,-0.5f,-0.5f};
        const float cy8[8] = {-1.0f,-1.0f, 0.0f, 0.0f,-1.0f,-1.0f, 0.0f, 0.0f};
        const float cz8[8] = {-0.5f,-0.5f,-0.5f, 0.5f, 0.5f, 0.5f, 0.5f,-0.5f};

        float umin =  3.4e38f, umax = -3.4e38f, vmin = 3.4e38f, vmax = -3.4e38f;
#pragma unroll
        for (int i = 0; i < 8; i++) {
            float xc = d0 * cx8[i], yc = d1 * cy8[i], zc = d2 * cz8[i];
            float bx =  cs * xc + sn * zc + pxl;
            float by =  yc + h;
            float bz = -sn * xc + cs * zc + depth;
            float up = Km[0]*bx + Km[1]*by + Km[2]*bz;
            float vp = Km[3]*bx + Km[4]*by + Km[5]*bz;
            float wp = Km[6]*bx + Km[7]*by + Km[8]*bz;
            float u = up / wp, v = vp / wp;
            umin = fminf(umin, u); umax = fmaxf(umax, u);
            vmin = fminf(vmin, v); vmax = fmaxf(vmax, v);
        }
        float img_w = size2[0], img_h = size2[1];
        float xmin = fminf(fmaxf(umin, 0.0f), img_w);
        float xmax = fminf(fmaxf(umax, 0.0f), img_w);
        float ymin = fminf(fmaxf(vmin, 0.0f), img_h);
        float ymax = fminf(fmaxf(vmax, 0.0f), img_h);

        float keep = (score > 0.25f) ? 1.0f : 0.0f;

        float o[14];
        o[0]  = (float)clsI;
        o[1]  = alpha;
        o[2]  = xmin; o[3] = ymin; o[4] = xmax; o[5] = ymax;
        o[6]  = d1;   o[7] = d2;   o[8] = d0;          // roll(dims, -1)
        o[9]  = pxl;  o[10] = h;   o[11] = depth;
        o[12] = roty;
        o[13] = score;

        float* dst = out + (size_t)(b * KDET + tid) * 14;
#pragma unroll
        for (int c = 0; c < 14; c++) dst[c] = o[c] * keep;
    }
}

// ---------------- launch ----------------
extern "C" void kernel_launch(void* const* d_in, const int* in_sizes, int n_in,
                              void* d_out, int out_size) {
    const float* hm    = (const float*)d_in[0];
    const float* reg   = (const float*)d_in[1];
    const float* trans = (const float*)d_in[2];
    const float* Kmat  = (const float*)d_in[3];
    const float* size2 = (const float*)d_in[4];
    const float* hcam  = (const float*)d_in[5];
    const float* dims  = (const float*)d_in[6];
    float* out = (float*)d_out;

    zero_counters<<<1, 128>>>();
    nms_collect<<<BC * NBLK_PER_SLICE, BLKNMS>>>(hm);
    select_topk<<<BC, 256>>>();
    finalize<<<Bb, 256>>>(reg, trans, Kmat, size2, hcam, dims, out);
}

// round 9
// speedup vs baseline: 3.5232x; 1.3375x over previous
#include <cuda_runtime.h>
#include <math.h>

// Problem constants (fixed shapes)
#define Bb 32
#define Cc 3
#define Hh 256
#define Ww 832
#define HWsz (Hh*Ww)          // 212992
#define BC (Bb*Cc)            // 96
#define KDET 100
#define QPR (Ww/4)            // 208 float4-quads per row

#define R_TILE 8
#define TROWS (R_TILE + 2)            // 10
#define NTILES (Hh / R_TILE)          // 32 tiles per slice
#define NMS_T 512
#define NQ (R_TILE * QPR)             // 1664 quads per tile

#define PI_F 3.14159265358979323846f
#define HALF_PI_F 1.57079632679489661923f

// ---------------- scratch (device globals; no runtime allocation) ----------------
__device__ unsigned long long g_cand[(size_t)BC * HWsz];   // worst-case survivor list
__device__ int                g_cnt[BC];
__device__ unsigned long long g_top1[BC * KDET];           // per-(b,c) top-100 keys

// key layout: [63:32] = float bits of value (value >= 0 so monotonic as uint)
//             [31:0]  = 0xFFFFFFFF - pixel_index  (larger = smaller index)
// descending key sort == jax top_k order (desc value, stable lower-index-first)

__global__ void zero_counters() {
    int i = threadIdx.x;
    if (i < BC) g_cnt[i] = 0;
}

__device__ __forceinline__ float fmax3(float a, float b, float c) {
    return fmaxf(a, fmaxf(b, c));
}

// ---------------- kernel 1: smem-tiled 3x3 NMS, atomic-free compaction ----------------
__global__ void nms_collect(const float* __restrict__ hm) {
    __shared__ float tile[TROWS][Ww];          // 10 x 832 floats = 33280 B
    __shared__ int   wsum[NMS_T / 32];
    __shared__ int   wbase[NMS_T / 32];
    __shared__ int   s_gbase;

    int slice = blockIdx.x / NTILES;           // bc in [0,96)
    int tidx  = blockIdx.x - slice * NTILES;   // tile in [0,32)
    int y0    = tidx * R_TILE;
    int tid   = threadIdx.x;
    unsigned lane = tid & 31u;
    int wid = tid >> 5;

    const float ninf = __int_as_float(0xff800000);
    const float* base = hm + (size_t)slice * HWsz;

    // stage rows y0-1 .. y0+R_TILE into smem (halo rows beyond image -> -inf)
    for (int i = tid; i < TROWS * QPR; i += NMS_T) {
        int r = i / QPR, q = i - r * QPR;
        int gy = y0 - 1 + r;
        float4 v;
        if ((unsigned)gy < (unsigned)Hh) v = *(const float4*)(base + gy * Ww + q * 4);
        else v = make_float4(ninf, ninf, ninf, ninf);
        *(float4*)&tile[r][q * 4] = v;
    }
    __syncthreads();

    // phase A: 3x3-max predicate per pixel, record per-thread survivor bitmask
    unsigned mask = 0;
    int cnt = 0;
    int slot = 0;
    for (int i = tid; i < NQ; i += NMS_T, slot++) {
        int ly = i / QPR, q = i - ly * QPR;
        int x4 = q * 4;
        float cm0 = ninf, cm1 = ninf, cm2 = ninf, cm3 = ninf, cm4 = ninf, cm5 = ninf;
        float v0 = 0.f, v1 = 0.f, v2 = 0.f, v3 = 0.f;
#pragma unroll
        for (int r = 0; r < 3; r++) {
            const float* row = &tile[ly + r][0];
            float4 f = *(const float4*)&row[x4];
            float l  = (x4 > 0)        ? row[x4 - 1] : ninf;
            float rr = (x4 + 4 < Ww)   ? row[x4 + 4] : ninf;
            cm0 = fmaxf(cm0, l);   cm1 = fmaxf(cm1, f.x); cm2 = fmaxf(cm2, f.y);
            cm3 = fmaxf(cm3, f.z); cm4 = fmaxf(cm4, f.w); cm5 = fmaxf(cm5, rr);
            if (r == 1) { v0 = f.x; v1 = f.y; v2 = f.z; v3 = f.w; }
        }
        if (v0 >= fmax3(cm0, cm1, cm2)) { mask |= 1u << (slot * 4 + 0); cnt++; }
        if (v1 >= fmax3(cm1, cm2, cm3)) { mask |= 1u << (slot * 4 + 1); cnt++; }
        if (v2 >= fmax3(cm2, cm3, cm4)) { mask |= 1u << (slot * 4 + 2); cnt++; }
        if (v3 >= fmax3(cm3, cm4, cm5)) { mask |= 1u << (slot * 4 + 3); cnt++; }
    }

    // block-wide exclusive scan of survivor counts (shuffle scan, no atomics)
    int inc = cnt;
#pragma unroll
    for (int d = 1; d < 32; d <<= 1) {
        int o = __shfl_up_sync(0xffffffffu, inc, d);
        if ((int)lane >= d) inc += o;
    }
    if (lane == 31) wsum[wid] = inc;
    __syncthreads();
    if (wid == 0) {
        int s = (lane < NMS_T / 32) ? wsum[lane] : 0;
#pragma unroll
        for (int d = 1; d < NMS_T / 32; d <<= 1) {
            int o = __shfl_up_sync(0xffffffffu, s, d);
            if ((int)lane >= d) s += o;
        }
        if (lane < NMS_T / 32) wbase[lane] = s - wsum[lane];
        if (lane == NMS_T / 32 - 1) s_gbase = atomicAdd(&g_cnt[slice], s);
    }
    __syncthreads();

    // phase B: write survivors at deterministic offsets
    int off = s_gbase + wbase[wid] + (inc - cnt);
    unsigned long long* dst = g_cand + (size_t)slice * HWsz;
    slot = 0;
    for (int i = tid; i < NQ; i += NMS_T, slot++) {
        unsigned mb = (mask >> (slot * 4)) & 0xFu;
        if (!mb) continue;
        int ly = i / QPR, q = i - ly * QPR;
        int x4 = q * 4;
        const float* row = &tile[ly + 1][0];
        while (mb) {
            int j = __ffs(mb) - 1; mb &= mb - 1;
            float v = row[x4 + j];
            unsigned pix = (unsigned)((y0 + ly) * Ww + x4 + j);
            dst[off++] = ((unsigned long long)__float_as_uint(v) << 32) |
                         (unsigned long long)(0xFFFFFFFFu - pix);
        }
    }
}

// ---------------- bitonic sort (descending) ----------------
template <int M>
__device__ void bitonic_desc(unsigned long long* buf, int tid, int nt) {
    for (int k = 2; k <= M; k <<= 1) {
        for (int j = k >> 1; j > 0; j >>= 1) {
            for (int i = tid; i < M; i += nt) {
                int ij = i ^ j;
                if (ij > i) {
                    bool dir = ((i & k) == 0);          // true -> descending segment
                    unsigned long long a = buf[i], b = buf[ij];
                    if ((a < b) == dir) { buf[i] = b; buf[ij] = a; }
                }
            }
            __syncthreads();
        }
    }
}

// ---------------- kernel 2: per-(b,c) exact top-100 via 2-level radix select ----------------
__global__ void select_topk() {
    __shared__ int hist[4096];
    __shared__ unsigned long long buf[2048];
    __shared__ int s_b1, s_pre1, s_thr, s_m;

    int bc  = blockIdx.x;
    int tid = threadIdx.x;
    int nt  = blockDim.x;
    int n   = g_cnt[bc];
    const unsigned long long* cand = g_cand + (size_t)bc * HWsz;

    for (int i = tid; i < 4096; i += nt) hist[i] = 0;
    if (tid == 0) { s_b1 = -1; s_pre1 = 0; s_thr = 0; s_m = 0; }
    __syncthreads();

    // level 1: 12-bit bins of top value bits (key >> 52)
    for (int i = tid; i < n; i += nt) atomicAdd(&hist[(int)(cand[i] >> 52)], 1);
    __syncthreads();
    if (tid == 0) {
        int cum = 0;
        for (int b = 4095; b >= 0; b--) {
            int c = hist[b];
            if (cum + c >= KDET) { s_b1 = b; s_pre1 = cum; break; }
            cum += c;
        }
        if (s_b1 < 0) { s_b1 = 0; s_pre1 = 0; }   // fewer than K candidates: take all
    }
    __syncthreads();
    int b1 = s_b1;

    // level 2: next 8 bits within bucket b1
    for (int i = tid; i < 256; i += nt) hist[i] = 0;
    __syncthreads();
    for (int i = tid; i < n; i += nt) {
        unsigned long long k = cand[i];
        if ((int)(k >> 52) == b1) atomicAdd(&hist[(int)((k >> 44) & 255)], 1);
    }
    __syncthreads();
    if (tid == 0) {
        int cum = s_pre1;
        int b2sel = 0;
        for (int b = 255; b >= 0; b--) {
            int c = hist[b];
            if (cum + c >= KDET) { b2sel = b; break; }
            cum += c;
        }
        s_thr = (b1 << 8) | b2sel;
    }
    __syncthreads();

    // collect everything at/above the 20-bit threshold
    unsigned long long thr = (unsigned long long)s_thr;
    for (int i = tid; i < n; i += nt) {
        unsigned long long k = cand[i];
        if ((k >> 44) >= thr) {
            int p = atomicAdd(&s_m, 1);
            if (p < 2048) buf[p] = k;
        }
    }
    __syncthreads();
    int m = min(s_m, 2048);

    if (m <= 512) {
        for (int i = tid + m; i < 512; i += nt) buf[i] = 0xFFFFFFFFull;
        __syncthreads();
        bitonic_desc<512>(buf, tid, nt);
    } else {
        for (int i = tid + m; i < 2048; i += nt) buf[i] = 0xFFFFFFFFull;
        __syncthreads();
        bitonic_desc<2048>(buf, tid, nt);
    }

    if (tid < KDET) g_top1[bc * KDET + tid] = buf[tid];
}

// ---------------- kernel 3: per-batch 300->100 top-k + geometry epilogue ----------------
__global__ void finalize(const float* __restrict__ reg,
                         const float* __restrict__ trans,
                         const float* __restrict__ Kmat,
                         const float* __restrict__ size2,
                         const float* __restrict__ hcam,
                         const float* __restrict__ dimsIn,
                         float* __restrict__ out) {
    __shared__ unsigned long long buf[512];
    __shared__ unsigned pixs[300];
    __shared__ float s_reg[300][4];

    int b = blockIdx.x, tid = threadIdx.x, nt = blockDim.x;

    for (int i = tid; i < 512; i += nt) {
        if (i < 300) {
            unsigned long long k1 = g_top1[b * 300 + i];   // i = c*100 + j
            unsigned pix = 0xFFFFFFFFu - (unsigned)(k1 & 0xFFFFFFFFu);
            if (pix >= (unsigned)HWsz) pix = 0;
            pixs[i] = pix;
            // re-key with flattened C*K position for the second-stage tie-break
            buf[i] = (k1 & 0xFFFFFFFF00000000ull) |
                     (unsigned long long)(0xFFFFFFFFu - (unsigned)i);
        } else {
            buf[i] = 0ull;
        }
    }
    __syncthreads();

    // Prefetch all candidates' regression gathers (parallel MLP instead of a
    // post-sort dependent latency chain). Ordered before use by the sort's syncs.
    const float* rb = reg + (size_t)b * 4 * HWsz;
    for (int i = tid; i < 300; i += nt) {
        unsigned pix = pixs[i];
        s_reg[i][0] = rb[0 * HWsz + pix];
        s_reg[i][1] = rb[1 * HWsz + pix];
        s_reg[i][2] = rb[2 * HWsz + pix];
        s_reg[i][3] = rb[3 * HWsz + pix];
    }

    bitonic_desc<512>(buf, tid, nt);

    if (tid < KDET) {
        unsigned long long k = buf[tid];
        float score = __uint_as_float((unsigned)(k >> 32));
        unsigned flat = 0xFFFFFFFFu - (unsigned)(k & 0xFFFFFFFFu);
        int clsI = 0; unsigned pix = 0;
        float dv_delta = 0.f, off_u = 0.f, ori0 = 0.f, ori1 = 0.f;
        if (flat < 300u) {
            clsI = flat / 100; pix = pixs[flat];
            dv_delta = s_reg[flat][0];
            off_u    = s_reg[flat][1];
            ori0     = s_reg[flat][2];
            ori1     = s_reg[flat][3];
        }

        int ysI = pix / Ww;
        int xsI = pix - ysI * Ww;
        float xs = (float)xsI, ys = (float)ysI;

        // 3x3 inverse of trans_mat (first row needed for img_x)
        const float* T = trans + b * 9;
        float a00=T[0],a01=T[1],a02=T[2],a10=T[3],a11=T[4],a12=T[5],a20=T[6],a21=T[7],a22=T[8];
        float det = a00*(a11*a22 - a12*a21) - a01*(a10*a22 - a12*a20) + a02*(a10*a21 - a11*a20);
        float id = 1.0f / det;
        float i00=(a11*a22-a12*a21)*id, i01=(a02*a21-a01*a22)*id, i02=(a01*a12-a02*a11)*id;

        float ptx = xs + off_u, pty = ys;
        float img_x = i00*ptx + i01*pty + i02;

        const float* Km = Kmat + b * 9;
        float fx = Km[0], cxk = Km[2], fy = Km[4];

        float h = hcam[b];
        float d0 = dimsIn[b*3+0], d1 = dimsIn[b*3+1], d2 = dimsIn[b*3+2];
        if (!isfinite(d0)) d0 = 3.88f;
        if (!isfinite(d1)) d1 = 1.63f;
        if (!isfinite(d2)) d2 = 1.53f;

        float h_ref = h - d1 * 0.5f;
        float fyh = fy * fabsf(h_ref);
        float log_dv_ref = logf(fmaxf(fyh, 1e-7f) / 28.01f);
        float log_dv = fminf(fmaxf(log_dv_ref + dv_delta, -4.0f), 8.0f);
        float depth = fminf(fmaxf(fyh * expf(-log_dv), 0.5f), 120.0f);
        float pxl = (img_x - cxk) * depth / fx;

        float ray = atanf(pxl / (depth + 1e-7f));
        float alpha = atanf(ori0 / (ori1 + 1e-7f)) + (ori1 >= 0.0f ? -HALF_PI_F : HALF_PI_F);
        float roty = alpha + ray;
        if (roty >  PI_F) roty -= 2.0f * PI_F;
        if (roty < -PI_F) roty += 2.0f * PI_F;
        float cs = cosf(roty), sn = sinf(roty);

        const float cx8[8] = {-0.5f, 0.5f, 0.5f, 0.5f, 0.5f,-0.5f,-0.5f,-0.5f};
        const float cy8[8] = {-1.0f,-1.0f, 0.0f, 0.0f,-1.0f,-1.0f, 0.0f, 0.0f};
        const float cz8[8] = {-0.5f,-0.5f,-0.5f, 0.5f, 0.5f, 0.5f, 0.5f,-0.5f};

        float umin =  3.4e38f, umax = -3.4e38f, vmin = 3.4e38f, vmax = -3.4e38f;
#pragma unroll
        for (int i = 0; i < 8; i++) {
            float xc = d0 * cx8[i], yc = d1 * cy8[i], zc = d2 * cz8[i];
            float bx =  cs * xc + sn * zc + pxl;
            float by =  yc + h;
            float bz = -sn * xc + cs * zc + depth;
            float up = Km[0]*bx + Km[1]*by + Km[2]*bz;
            float vp = Km[3]*bx + Km[4]*by + Km[5]*bz;
            float wp = Km[6]*bx + Km[7]*by + Km[8]*bz;
            float u = up / wp, v = vp / wp;
            umin = fminf(umin, u); umax = fmaxf(umax, u);
            vmin = fminf(vmin, v); vmax = fmaxf(vmax, v);
        }
        float img_w = size2[0], img_h = size2[1];
        float xmin = fminf(fmaxf(umin, 0.0f), img_w);
        float xmax = fminf(fmaxf(umax, 0.0f), img_w);
        float ymin = fminf(fmaxf(vmin, 0.0f), img_h);
        float ymax = fminf(fmaxf(vmax, 0.0f), img_h);

        float keep = (score > 0.25f) ? 1.0f : 0.0f;

        float o[14];
        o[0]  = (float)clsI;
        o[1]  = alpha;
        o[2]  = xmin; o[3] = ymin; o[4] = xmax; o[5] = ymax;
        o[6]  = d1;   o[7] = d2;   o[8] = d0;          // roll(dims, -1)
        o[9]  = pxl;  o[10] = h;   o[11] = depth;
        o[12] = roty;
        o[13] = score;

        float* dst = out + (size_t)(b * KDET + tid) * 14;
#pragma unroll
        for (int c = 0; c < 14; c++) dst[c] = o[c] * keep;
    }
}

// ---------------- launch ----------------
extern "C" void kernel_launch(void* const* d_in, const int* in_sizes, int n_in,
                              void* d_out, int out_size) {
    const float* hm    = (const float*)d_in[0];
    const float* reg   = (const float*)d_in[1];
    const float* trans = (const float*)d_in[2];
    const float* Kmat  = (const float*)d_in[3];
    const float* size2 = (const float*)d_in[4];
    const float* hcam  = (const float*)d_in[5];
    const float* dims  = (const float*)d_in[6];
    float* out = (float*)d_out;

    zero_counters<<<1, 96>>>();
    nms_collect<<<BC * NTILES, NMS_T>>>(hm);
    select_topk<<<BC, 512>>>();
    finalize<<<Bb, 512>>>(reg, trans, Kmat, size2, hcam, dims, out);
}